// round 2
// baseline (speedup 1.0000x reference)
#include <cuda_runtime.h>
#include <cstdint>

#define NN 50000
#define EE 600000
#define DD 128
#define NEG 0.2f

// Scratch (device globals: no allocation allowed)
__device__ float g_deg[NN];
__device__ float g_dis[NN];
__device__ float g_hw [NN * DD];   // x @ W
__device__ float g_agg[NN * DD];   // scatter accumulator
__device__ float g_h  [NN * DD];   // current activation

// ---------------- degree / norm ----------------
__global__ void k_zero(float* p, int n) {
    int i = blockIdx.x * blockDim.x + threadIdx.x;
    if (i < n) p[i] = 0.f;
}

__global__ void k_count(const int* __restrict__ col, float* __restrict__ deg, int ne) {
    int e = blockIdx.x * blockDim.x + threadIdx.x;
    if (e < ne) atomicAdd(&deg[col[e]], 1.f);
}

__global__ void k_dis(const float* __restrict__ deg, float* __restrict__ dis, int n) {
    int i = blockIdx.x * blockDim.x + threadIdx.x;
    if (i < n) dis[i] = rsqrtf(deg[i] + 1.f);
}

// ---------------- GEMM: C[n,128] = A[n,128] @ W[128,128] ----------------
// 256 threads/block, 64 rows/block, thread tile 8 rows x 4 cols
__global__ void k_gemm(const float* __restrict__ A, const float* __restrict__ W,
                       float* __restrict__ C, int nrows) {
    __shared__ float Ws[32 * 128];  // 16 KB
    __shared__ float Xs[64 * 32];   // 8 KB
    int t  = threadIdx.x;
    int tx = t & 31;        // col group: 32 groups * 4 cols
    int ty = t >> 5;        // row group: 8 groups * 8 rows
    int row0 = blockIdx.x * 64;

    float acc[8][4];
#pragma unroll
    for (int i = 0; i < 8; i++)
#pragma unroll
        for (int j = 0; j < 4; j++) acc[i][j] = 0.f;

    for (int k0 = 0; k0 < 128; k0 += 32) {
        for (int i = t; i < 32 * 128; i += 256)
            Ws[i] = W[(k0 + (i >> 7)) * 128 + (i & 127)];
        for (int i = t; i < 64 * 32; i += 256) {
            int r = i >> 5, k = i & 31;
            int gr = row0 + r;
            Xs[i] = (gr < nrows) ? A[gr * 128 + k0 + k] : 0.f;
        }
        __syncthreads();
#pragma unroll
        for (int kk = 0; kk < 32; kk++) {
            float4 w = *(const float4*)&Ws[kk * 128 + tx * 4];
            float xv[8];
#pragma unroll
            for (int i = 0; i < 8; i++) xv[i] = Xs[(ty * 8 + i) * 32 + kk];
#pragma unroll
            for (int i = 0; i < 8; i++) {
                acc[i][0] += xv[i] * w.x;
                acc[i][1] += xv[i] * w.y;
                acc[i][2] += xv[i] * w.z;
                acc[i][3] += xv[i] * w.w;
            }
        }
        __syncthreads();
    }
#pragma unroll
    for (int i = 0; i < 8; i++) {
        int r = row0 + ty * 8 + i;
        if (r < nrows) {
            float4 v = make_float4(acc[i][0], acc[i][1], acc[i][2], acc[i][3]);
            *(float4*)&C[r * 128 + tx * 4] = v;
        }
    }
}

// ---------------- edge scatter: agg[col] += hw[row] * dis[row]*dis[col] ----------------
// 32 lanes per edge, float4 gather, 4 scalar atomics
__global__ void k_scatter(const int* __restrict__ row, const int* __restrict__ col,
                          const float* __restrict__ dis, const float* __restrict__ hw,
                          float* __restrict__ agg, int ne) {
    int gid  = blockIdx.x * blockDim.x + threadIdx.x;
    int e    = gid >> 5;
    int lane = gid & 31;
    if (e >= ne) return;
    int r = row[e];
    int c = col[e];
    float norm = dis[r] * dis[c];
    float4 v = ((const float4*)&hw[r * DD])[lane];
    float* dst = &agg[c * DD + lane * 4];
    atomicAdd(dst + 0, v.x * norm);
    atomicAdd(dst + 1, v.y * norm);
    atomicAdd(dst + 2, v.z * norm);
    atomicAdd(dst + 3, v.w * norm);
}

// ---------------- combine + bias + (residual) + leaky ----------------
__global__ void k_combine(const float* __restrict__ agg, const float* __restrict__ hw,
                          const float* __restrict__ dis, const float* __restrict__ b,
                          const float* __restrict__ hprev, float* __restrict__ hout,
                          int n, int residual) {
    int idx = blockIdx.x * blockDim.x + threadIdx.x;   // float4 index
    if (idx >= n * 32) return;
    int node = idx >> 5;
    int q    = idx & 31;
    float d  = dis[node];
    float d2 = d * d;
    float4 a  = ((const float4*)agg)[idx];
    float4 hv = ((const float4*)hw)[idx];
    float4 bv = ((const float4*)b)[q];
    float4 v;
    v.x = a.x + hv.x * d2 + bv.x;
    v.y = a.y + hv.y * d2 + bv.y;
    v.z = a.z + hv.z * d2 + bv.z;
    v.w = a.w + hv.w * d2 + bv.w;
    if (residual) {
        float4 p = ((const float4*)hprev)[idx];
        v.x += p.x; v.y += p.y; v.z += p.z; v.w += p.w;
    }
    v.x = (v.x > 0.f) ? v.x : NEG * v.x;
    v.y = (v.y > 0.f) ? v.y : NEG * v.y;
    v.z = (v.z > 0.f) ? v.z : NEG * v.z;
    v.w = (v.w > 0.f) ? v.w : NEG * v.w;
    ((float4*)hout)[idx] = v;
}

// ---------------- logits: out[n] = h[n,:] . lw + lb ----------------
__global__ void k_logits(const float* __restrict__ h, const float* __restrict__ lw,
                         const float* __restrict__ lb, float* __restrict__ out, int n) {
    int gid  = blockIdx.x * blockDim.x + threadIdx.x;
    int node = gid >> 5;
    int lane = gid & 31;
    if (node >= n) return;
    float4 hv = ((const float4*)&h[node * DD])[lane];
    float4 wv = ((const float4*)lw)[lane];
    float s = hv.x * wv.x + hv.y * wv.y + hv.z * wv.z + hv.w * wv.w;
#pragma unroll
    for (int o = 16; o > 0; o >>= 1) s += __shfl_down_sync(0xffffffffu, s, o);
    if (lane == 0) out[node] = s + lb[0];
}

extern "C" void kernel_launch(void* const* d_in, const int* in_sizes, int n_in,
                              void* d_out, int out_size) {
    const float* x   = (const float*)d_in[0];
    const int*   ei  = (const int*)d_in[1];
    const float* W1  = (const float*)d_in[2];
    const float* b1  = (const float*)d_in[3];
    const float* W2  = (const float*)d_in[4];
    const float* b2  = (const float*)d_in[5];
    const float* W3  = (const float*)d_in[6];
    const float* b3  = (const float*)d_in[7];
    const float* lw  = (const float*)d_in[8];
    const float* lb  = (const float*)d_in[9];
    float* out = (float*)d_out;

    const int ne = in_sizes[1] / 2;      // 600000
    const int n  = in_sizes[0] / DD;     // 50000
    const int* row = ei;
    const int* col = ei + ne;

    float *deg, *dis, *hw, *agg, *h;
    cudaGetSymbolAddress((void**)&deg, g_deg);
    cudaGetSymbolAddress((void**)&dis, g_dis);
    cudaGetSymbolAddress((void**)&hw,  g_hw);
    cudaGetSymbolAddress((void**)&agg, g_agg);
    cudaGetSymbolAddress((void**)&h,   g_h);

    const int T = 256;
    int gemm_grid    = (n + 63) / 64;
    int vec_grid     = (n * 32 + T - 1) / T;       // N*D/4 elements
    int scatter_grid = (int)(((long long)ne * 32 + T - 1) / T);
    int aggvec       = n * DD;                     // floats to zero

    // degree + norm
    k_zero <<<(n + T - 1) / T, T>>>(deg, n);
    k_count<<<(ne + T - 1) / T, T>>>(col, deg, ne);
    k_dis  <<<(n + T - 1) / T, T>>>(deg, dis, n);

    // ---- layer 1 ----
    k_gemm   <<<gemm_grid, T>>>(x, W1, hw, n);
    k_zero   <<<(aggvec + T - 1) / T, T>>>(agg, aggvec);
    k_scatter<<<scatter_grid, T>>>(row, col, dis, hw, agg, ne);
    k_combine<<<vec_grid, T>>>(agg, hw, dis, b1, nullptr, h, n, 0);

    // ---- layer 2 ----
    k_gemm   <<<gemm_grid, T>>>(h, W2, hw, n);
    k_zero   <<<(aggvec + T - 1) / T, T>>>(agg, aggvec);
    k_scatter<<<scatter_grid, T>>>(row, col, dis, hw, agg, ne);
    k_combine<<<vec_grid, T>>>(agg, hw, dis, b2, h, h, n, 1);

    // ---- layer 3 ----
    k_gemm   <<<gemm_grid, T>>>(h, W3, hw, n);
    k_zero   <<<(aggvec + T - 1) / T, T>>>(agg, aggvec);
    k_scatter<<<scatter_grid, T>>>(row, col, dis, hw, agg, ne);
    k_combine<<<vec_grid, T>>>(agg, hw, dis, b3, h, h, n, 1);

    // ---- head ----
    k_logits<<<(n * 32 + T - 1) / T, T>>>(h, lw, lb, out, n);
}

// round 3
// speedup vs baseline: 2.6771x; 2.6771x over previous
#include <cuda_runtime.h>
#include <cstdint>

#define NN 50000
#define EE 600000
#define DD 128
#define NEG 0.2f
#define SCAN_B 256

// Scratch (device globals: no allocation allowed)
__device__ int   g_cnt[NN];
__device__ int   g_cur[NN];
__device__ int   g_rowptr[NN + 1];
__device__ int   g_src[EE];
__device__ int   g_bsum[SCAN_B];
__device__ float g_dis[NN];
__device__ float g_hw [NN * DD];   // x @ W
__device__ float g_h  [NN * DD];   // current activation

// ---------------- init / degree ----------------
__global__ void k_zero_int(int* p, int n) {
    int i = blockIdx.x * blockDim.x + threadIdx.x;
    if (i < n) p[i] = 0;
}

__global__ void k_count(const int* __restrict__ col, int* __restrict__ cnt, int ne) {
    int e = blockIdx.x * blockDim.x + threadIdx.x;
    if (e < ne) atomicAdd(&cnt[col[e]], 1);
}

__global__ void k_dis(const int* __restrict__ cnt, float* __restrict__ dis, int n) {
    int i = blockIdx.x * blockDim.x + threadIdx.x;
    if (i < n) dis[i] = rsqrtf((float)cnt[i] + 1.f);
}

// ---------------- exclusive scan of cnt -> rowptr ----------------
__global__ void k_scan1(const int* __restrict__ cnt, int* __restrict__ rowptr,
                        int* __restrict__ bsum, int n) {
    __shared__ int sh[SCAN_B];
    int t = threadIdx.x;
    int i = blockIdx.x * SCAN_B + t;
    int v = (i < n) ? cnt[i] : 0;
    sh[t] = v; __syncthreads();
#pragma unroll
    for (int o = 1; o < SCAN_B; o <<= 1) {
        int x = (t >= o) ? sh[t - o] : 0;
        __syncthreads();
        sh[t] += x;
        __syncthreads();
    }
    if (i < n) rowptr[i] = sh[t] - v;          // exclusive
    if (t == SCAN_B - 1) bsum[blockIdx.x] = sh[t];
}

__global__ void k_scan2(int* __restrict__ bsum, int nb) {
    __shared__ int sh[SCAN_B];
    int t = threadIdx.x;
    int v = (t < nb) ? bsum[t] : 0;
    sh[t] = v; __syncthreads();
#pragma unroll
    for (int o = 1; o < SCAN_B; o <<= 1) {
        int x = (t >= o) ? sh[t - o] : 0;
        __syncthreads();
        sh[t] += x;
        __syncthreads();
    }
    if (t < nb) bsum[t] = sh[t] - v;           // exclusive
}

__global__ void k_scan3(int* __restrict__ rowptr, const int* __restrict__ bsum,
                        int n, int ne) {
    int i = blockIdx.x * SCAN_B + threadIdx.x;
    if (i < n) rowptr[i] += bsum[blockIdx.x];
    if (i == 0) rowptr[n] = ne;
}

// ---------------- bucket edges by destination ----------------
__global__ void k_bucket(const int* __restrict__ row, const int* __restrict__ col,
                         const int* __restrict__ rowptr, int* __restrict__ cur,
                         int* __restrict__ src, int ne) {
    int e = blockIdx.x * blockDim.x + threadIdx.x;
    if (e >= ne) return;
    int c = col[e];
    int p = rowptr[c] + atomicAdd(&cur[c], 1);
    src[p] = row[e];
}

// ---------------- GEMM: C[n,128] = A[n,128] @ W[128,128] ----------------
// 256 threads (16x16), 128-row tile, 8x8 per thread
__global__ void __launch_bounds__(256) k_gemm(const float* __restrict__ A,
                                              const float* __restrict__ W,
                                              float* __restrict__ C, int nrows) {
    __shared__ float Xs[8][132];
    __shared__ float Ws[8][132];
    int t  = threadIdx.x;
    int tx = t & 15;
    int ty = t >> 4;
    int row0 = blockIdx.x * 128;

    float acc[8][8];
#pragma unroll
    for (int i = 0; i < 8; i++)
#pragma unroll
        for (int j = 0; j < 8; j++) acc[i][j] = 0.f;

    int lr = t >> 1;        // 0..127 row for X load
    int lq = t & 1;         // which float4 of the 8-wide k chunk
    int wk = t >> 5;        // 0..7 k-row for W load
    int wc = (t & 31) << 2; // col

    for (int k0 = 0; k0 < 128; k0 += 8) {
        int gr = row0 + lr;
        float4 xv = (gr < nrows) ? ((const float4*)A)[gr * 32 + (k0 >> 2) + lq]
                                 : make_float4(0.f, 0.f, 0.f, 0.f);
        Xs[lq * 4 + 0][lr] = xv.x;
        Xs[lq * 4 + 1][lr] = xv.y;
        Xs[lq * 4 + 2][lr] = xv.z;
        Xs[lq * 4 + 3][lr] = xv.w;
        *(float4*)&Ws[wk][wc] = ((const float4*)W)[(k0 + wk) * 32 + (wc >> 2)];
        __syncthreads();
#pragma unroll
        for (int kk = 0; kk < 8; kk++) {
            float xr[8], wr[8];
            *(float4*)&xr[0] = *(const float4*)&Xs[kk][ty * 8];
            *(float4*)&xr[4] = *(const float4*)&Xs[kk][ty * 8 + 4];
            *(float4*)&wr[0] = *(const float4*)&Ws[kk][tx * 8];
            *(float4*)&wr[4] = *(const float4*)&Ws[kk][tx * 8 + 4];
#pragma unroll
            for (int i = 0; i < 8; i++)
#pragma unroll
                for (int j = 0; j < 8; j++)
                    acc[i][j] += xr[i] * wr[j];
        }
        __syncthreads();
    }
#pragma unroll
    for (int i = 0; i < 8; i++) {
        int gr = row0 + ty * 8 + i;
        if (gr < nrows) {
            *(float4*)&C[gr * 128 + tx * 8]     = make_float4(acc[i][0], acc[i][1], acc[i][2], acc[i][3]);
            *(float4*)&C[gr * 128 + tx * 8 + 4] = make_float4(acc[i][4], acc[i][5], acc[i][6], acc[i][7]);
        }
    }
}

// ---------------- pull aggregation (fused combine) ----------------
// one warp per node; lane handles float4 slice of 128 features
__global__ void k_pull(const int* __restrict__ rowptr, const int* __restrict__ src,
                       const float* __restrict__ dis, const float* __restrict__ hw,
                       const float* __restrict__ b, const float* __restrict__ hprev,
                       float* __restrict__ hout, int n, int residual) {
    int gid  = blockIdx.x * blockDim.x + threadIdx.x;
    int node = gid >> 5;
    int lane = gid & 31;
    if (node >= n) return;
    int s0 = rowptr[node];
    int s1 = rowptr[node + 1];
    float4 acc = make_float4(0.f, 0.f, 0.f, 0.f);
    for (int j = s0; j < s1; j++) {
        int s = src[j];
        float w = dis[s];
        float4 v = ((const float4*)hw)[s * 32 + lane];
        acc.x += v.x * w; acc.y += v.y * w; acc.z += v.z * w; acc.w += v.w * w;
    }
    float d  = dis[node];
    float d2 = d * d;
    float4 hv = ((const float4*)hw)[node * 32 + lane];
    float4 bv = ((const float4*)b)[lane];
    float4 o;
    o.x = acc.x * d + hv.x * d2 + bv.x;
    o.y = acc.y * d + hv.y * d2 + bv.y;
    o.z = acc.z * d + hv.z * d2 + bv.z;
    o.w = acc.w * d + hv.w * d2 + bv.w;
    if (residual) {
        float4 p = ((const float4*)hprev)[node * 32 + lane];
        o.x += p.x; o.y += p.y; o.z += p.z; o.w += p.w;
    }
    o.x = (o.x > 0.f) ? o.x : NEG * o.x;
    o.y = (o.y > 0.f) ? o.y : NEG * o.y;
    o.z = (o.z > 0.f) ? o.z : NEG * o.z;
    o.w = (o.w > 0.f) ? o.w : NEG * o.w;
    ((float4*)hout)[node * 32 + lane] = o;
}

// ---------------- layer-3 pull fused with logits head ----------------
__global__ void k_pull_logits(const int* __restrict__ rowptr, const int* __restrict__ src,
                              const float* __restrict__ dis, const float* __restrict__ hw,
                              const float* __restrict__ b, const float* __restrict__ hprev,
                              const float* __restrict__ lw, const float* __restrict__ lb,
                              float* __restrict__ out, int n) {
    int gid  = blockIdx.x * blockDim.x + threadIdx.x;
    int node = gid >> 5;
    int lane = gid & 31;
    if (node >= n) return;
    int s0 = rowptr[node];
    int s1 = rowptr[node + 1];
    float4 acc = make_float4(0.f, 0.f, 0.f, 0.f);
    for (int j = s0; j < s1; j++) {
        int s = src[j];
        float w = dis[s];
        float4 v = ((const float4*)hw)[s * 32 + lane];
        acc.x += v.x * w; acc.y += v.y * w; acc.z += v.z * w; acc.w += v.w * w;
    }
    float d  = dis[node];
    float d2 = d * d;
    float4 hv = ((const float4*)hw)[node * 32 + lane];
    float4 bv = ((const float4*)b)[lane];
    float4 p  = ((const float4*)hprev)[node * 32 + lane];
    float4 o;
    o.x = acc.x * d + hv.x * d2 + bv.x + p.x;
    o.y = acc.y * d + hv.y * d2 + bv.y + p.y;
    o.z = acc.z * d + hv.z * d2 + bv.z + p.z;
    o.w = acc.w * d + hv.w * d2 + bv.w + p.w;
    o.x = (o.x > 0.f) ? o.x : NEG * o.x;
    o.y = (o.y > 0.f) ? o.y : NEG * o.y;
    o.z = (o.z > 0.f) ? o.z : NEG * o.z;
    o.w = (o.w > 0.f) ? o.w : NEG * o.w;
    float4 wv = ((const float4*)lw)[lane];
    float s = o.x * wv.x + o.y * wv.y + o.z * wv.z + o.w * wv.w;
#pragma unroll
    for (int off = 16; off > 0; off >>= 1) s += __shfl_down_sync(0xffffffffu, s, off);
    if (lane == 0) out[node] = s + lb[0];
}

extern "C" void kernel_launch(void* const* d_in, const int* in_sizes, int n_in,
                              void* d_out, int out_size) {
    const float* x   = (const float*)d_in[0];
    const int*   ei  = (const int*)d_in[1];
    const float* W1  = (const float*)d_in[2];
    const float* b1  = (const float*)d_in[3];
    const float* W2  = (const float*)d_in[4];
    const float* b2  = (const float*)d_in[5];
    const float* W3  = (const float*)d_in[6];
    const float* b3  = (const float*)d_in[7];
    const float* lw  = (const float*)d_in[8];
    const float* lb  = (const float*)d_in[9];
    float* out = (float*)d_out;

    const int ne = in_sizes[1] / 2;      // 600000
    const int n  = in_sizes[0] / DD;     // 50000
    const int* row = ei;
    const int* col = ei + ne;

    int *cnt, *cur, *rowptr, *src, *bsum;
    float *dis, *hw, *h;
    cudaGetSymbolAddress((void**)&cnt,    g_cnt);
    cudaGetSymbolAddress((void**)&cur,    g_cur);
    cudaGetSymbolAddress((void**)&rowptr, g_rowptr);
    cudaGetSymbolAddress((void**)&src,    g_src);
    cudaGetSymbolAddress((void**)&bsum,   g_bsum);
    cudaGetSymbolAddress((void**)&dis,    g_dis);
    cudaGetSymbolAddress((void**)&hw,     g_hw);
    cudaGetSymbolAddress((void**)&h,      g_h);

    const int T = 256;
    int nb        = (n + SCAN_B - 1) / SCAN_B;               // 196
    int gemm_grid = (n + 127) / 128;
    int pull_grid = (int)(((long long)n * 32 + T - 1) / T);  // warp per node

    // ---- CSC build (once, reused by all 3 layers) ----
    k_zero_int<<<(n + T - 1) / T, T>>>(cnt, n);
    k_zero_int<<<(n + T - 1) / T, T>>>(cur, n);
    k_count   <<<(ne + T - 1) / T, T>>>(col, cnt, ne);
    k_dis     <<<(n + T - 1) / T, T>>>(cnt, dis, n);
    k_scan1   <<<nb, SCAN_B>>>(cnt, rowptr, bsum, n);
    k_scan2   <<<1, SCAN_B>>>(bsum, nb);
    k_scan3   <<<nb, SCAN_B>>>(rowptr, bsum, n, ne);
    k_bucket  <<<(ne + T - 1) / T, T>>>(row, col, rowptr, cur, src, ne);

    // ---- layer 1 ----
    k_gemm<<<gemm_grid, T>>>(x, W1, hw, n);
    k_pull<<<pull_grid, T>>>(rowptr, src, dis, hw, b1, nullptr, h, n, 0);

    // ---- layer 2 ----
    k_gemm<<<gemm_grid, T>>>(h, W2, hw, n);
    k_pull<<<pull_grid, T>>>(rowptr, src, dis, hw, b2, h, h, n, 1);

    // ---- layer 3 (fused with logits head) ----
    k_gemm<<<gemm_grid, T>>>(h, W3, hw, n);
    k_pull_logits<<<pull_grid, T>>>(rowptr, src, dis, hw, b3, h, lw, lb, out, n);
}

// round 4
// speedup vs baseline: 3.4399x; 1.2849x over previous
#include <cuda_runtime.h>
#include <cstdint>

#define NN 50000
#define EE 600000
#define DD 128
#define NEG 0.2f
#define SCAN_B 256

#define AS_STRIDE 132
#define WS_STRIDE 136
#define SMEM_FLOATS (128 * AS_STRIDE + 128 * WS_STRIDE)

// Scratch (device globals: no allocation allowed)
__device__ int   g_cnt[NN];
__device__ int   g_cur[NN];
__device__ int   g_rowptr[NN + 1];
__device__ int   g_src[EE];
__device__ int   g_bsum[SCAN_B];
__device__ float g_dis[NN];
__device__ float g_hw [NN * DD];
__device__ float g_h  [NN * DD];

// ---------------- build helpers ----------------
__global__ void k_init(int* cnt, int* cur, int n) {
    int i = blockIdx.x * blockDim.x + threadIdx.x;
    if (i < n) { cnt[i] = 0; cur[i] = 0; }
}

__global__ void k_count(const int* __restrict__ col, int* __restrict__ cnt, int ne) {
    int e = blockIdx.x * blockDim.x + threadIdx.x;
    if (e < ne) atomicAdd(&cnt[col[e]], 1);
}

// exclusive scan pass 1 (also computes dis = rsqrt(deg+1))
__global__ void k_scan1(const int* __restrict__ cnt, int* __restrict__ rowptr,
                        int* __restrict__ bsum, float* __restrict__ dis, int n) {
    __shared__ int sh[SCAN_B];
    int t = threadIdx.x;
    int i = blockIdx.x * SCAN_B + t;
    int v = (i < n) ? cnt[i] : 0;
    if (i < n) dis[i] = rsqrtf((float)v + 1.f);
    sh[t] = v; __syncthreads();
#pragma unroll
    for (int o = 1; o < SCAN_B; o <<= 1) {
        int x = (t >= o) ? sh[t - o] : 0;
        __syncthreads();
        sh[t] += x;
        __syncthreads();
    }
    if (i < n) rowptr[i] = sh[t] - v;
    if (t == SCAN_B - 1) bsum[blockIdx.x] = sh[t];
}

__global__ void k_scan2(int* __restrict__ bsum, int nb) {
    __shared__ int sh[SCAN_B];
    int t = threadIdx.x;
    int v = (t < nb) ? bsum[t] : 0;
    sh[t] = v; __syncthreads();
#pragma unroll
    for (int o = 1; o < SCAN_B; o <<= 1) {
        int x = (t >= o) ? sh[t - o] : 0;
        __syncthreads();
        sh[t] += x;
        __syncthreads();
    }
    if (t < nb) bsum[t] = sh[t] - v;
}

__global__ void k_scan3(int* __restrict__ rowptr, const int* __restrict__ bsum,
                        int n, int ne) {
    int i = blockIdx.x * SCAN_B + threadIdx.x;
    if (i < n) rowptr[i] += bsum[blockIdx.x];
    if (i == 0) rowptr[n] = ne;
}

__global__ void k_bucket(const int* __restrict__ row, const int* __restrict__ col,
                         const int* __restrict__ rowptr, int* __restrict__ cur,
                         int* __restrict__ src, int ne) {
    int e = blockIdx.x * blockDim.x + threadIdx.x;
    if (e >= ne) return;
    int c = col[e];
    int p = rowptr[c] + atomicAdd(&cur[c], 1);
    src[p] = row[e];
}

// ---------------- TF32 helpers ----------------
__device__ __forceinline__ uint32_t f2tf32(float x) {
    uint32_t u;
    asm("cvt.rna.tf32.f32 %0, %1;" : "=r"(u) : "f"(x));
    return u;
}

__device__ __forceinline__ void split_tf32(float x, uint32_t& hi, uint32_t& lo) {
    hi = f2tf32(x);
    float hif = __uint_as_float(hi);
    lo = f2tf32(x - hif);
}

__device__ __forceinline__ void mma8(float* d, const uint32_t* a, uint32_t b0, uint32_t b1) {
    asm volatile(
        "mma.sync.aligned.m16n8k8.row.col.f32.tf32.tf32.f32 "
        "{%0,%1,%2,%3}, {%4,%5,%6,%7}, {%8,%9}, {%0,%1,%2,%3};"
        : "+f"(d[0]), "+f"(d[1]), "+f"(d[2]), "+f"(d[3])
        : "r"(a[0]), "r"(a[1]), "r"(a[2]), "r"(a[3]), "r"(b0), "r"(b1));
}

// ---------------- GEMM: C[n,128] = A[n,128] @ W[128,128], 3xTF32 ----------------
// 256 threads (8 warps), block tile 128x128. Warp tile 32(m) x 64(n).
__global__ void __launch_bounds__(256, 1) k_gemm(const float* __restrict__ A,
                                                 const float* __restrict__ W,
                                                 float* __restrict__ C, int nrows) {
    extern __shared__ float sm[];
    float* As = sm;                        // [128][AS_STRIDE]
    float* Ws = sm + 128 * AS_STRIDE;      // [128][WS_STRIDE]

    int t    = threadIdx.x;
    int lane = t & 31;
    int wid  = t >> 5;
    int warp_m = wid & 3;      // 0..3 -> 32 rows
    int warp_n = wid >> 2;     // 0..1 -> 64 cols
    int q  = lane >> 2;        // 0..7
    int r4 = lane & 3;         // 0..3
    int row0 = blockIdx.x * 128;

    // load A tile (row-major, float4) and W (row-major, float4)
#pragma unroll
    for (int i = 0; i < 16; i++) {
        int flat = i * 256 + t;            // float4 index, 4096 total
        int r  = flat >> 5;
        int kq = flat & 31;
        int gr = row0 + r;
        float4 v = (gr < nrows) ? ((const float4*)A)[gr * 32 + kq]
                                : make_float4(0.f, 0.f, 0.f, 0.f);
        *(float4*)&As[r * AS_STRIDE + kq * 4] = v;
        float4 w = ((const float4*)W)[flat];
        *(float4*)&Ws[(flat >> 5) * WS_STRIDE + kq * 4] = w;
    }
    __syncthreads();

    float acc[2][8][4];
#pragma unroll
    for (int mt = 0; mt < 2; mt++)
#pragma unroll
        for (int nt = 0; nt < 8; nt++)
#pragma unroll
            for (int j = 0; j < 4; j++) acc[mt][nt][j] = 0.f;

#pragma unroll 2
    for (int kk = 0; kk < 16; kk++) {
        int kb = kk * 8;
        uint32_t Ahi[2][4], Alo[2][4];
#pragma unroll
        for (int mt = 0; mt < 2; mt++) {
            int rb = warp_m * 32 + mt * 16;
            float a0 = As[(rb + q) * AS_STRIDE + kb + r4];
            float a1 = As[(rb + q + 8) * AS_STRIDE + kb + r4];
            float a2 = As[(rb + q) * AS_STRIDE + kb + r4 + 4];
            float a3 = As[(rb + q + 8) * AS_STRIDE + kb + r4 + 4];
            split_tf32(a0, Ahi[mt][0], Alo[mt][0]);
            split_tf32(a1, Ahi[mt][1], Alo[mt][1]);
            split_tf32(a2, Ahi[mt][2], Alo[mt][2]);
            split_tf32(a3, Ahi[mt][3], Alo[mt][3]);
        }
        uint32_t Bhi[8][2], Blo[8][2];
#pragma unroll
        for (int nt = 0; nt < 8; nt++) {
            int n = warp_n * 64 + nt * 8 + q;
            float b0 = Ws[(kb + r4) * WS_STRIDE + n];
            float b1 = Ws[(kb + r4 + 4) * WS_STRIDE + n];
            split_tf32(b0, Bhi[nt][0], Blo[nt][0]);
            split_tf32(b1, Bhi[nt][1], Blo[nt][1]);
        }
#pragma unroll
        for (int mt = 0; mt < 2; mt++)
#pragma unroll
            for (int nt = 0; nt < 8; nt++) {
                mma8(acc[mt][nt], Ahi[mt], Bhi[nt][0], Bhi[nt][1]);
                mma8(acc[mt][nt], Alo[mt], Bhi[nt][0], Bhi[nt][1]);
                mma8(acc[mt][nt], Ahi[mt], Blo[nt][0], Blo[nt][1]);
            }
    }

    // epilogue: c0,c1 -> (row=q, col=r4*2,+1); c2,c3 -> (row=q+8)
#pragma unroll
    for (int mt = 0; mt < 2; mt++) {
#pragma unroll
        for (int nt = 0; nt < 8; nt++) {
            int colb = warp_n * 64 + nt * 8 + r4 * 2;
            int ra = row0 + warp_m * 32 + mt * 16 + q;
            int rb = ra + 8;
            if (ra < nrows)
                *(float2*)&C[ra * 128 + colb] = make_float2(acc[mt][nt][0], acc[mt][nt][1]);
            if (rb < nrows)
                *(float2*)&C[rb * 128 + colb] = make_float2(acc[mt][nt][2], acc[mt][nt][3]);
        }
    }
}

// ---------------- pull aggregation (fused combine) ----------------
__global__ void k_pull(const int* __restrict__ rowptr, const int* __restrict__ src,
                       const float* __restrict__ dis, const float* __restrict__ hw,
                       const float* __restrict__ b, const float* __restrict__ hprev,
                       float* __restrict__ hout, int n, int residual) {
    int gid  = blockIdx.x * blockDim.x + threadIdx.x;
    int node = gid >> 5;
    int lane = gid & 31;
    if (node >= n) return;
    int s0 = rowptr[node];
    int s1 = rowptr[node + 1];
    float4 acc = make_float4(0.f, 0.f, 0.f, 0.f);
    int j = s0;
    for (; j + 1 < s1; j += 2) {
        int sA = src[j], sB = src[j + 1];
        float wA = dis[sA], wB = dis[sB];
        float4 vA = ((const float4*)hw)[sA * 32 + lane];
        float4 vB = ((const float4*)hw)[sB * 32 + lane];
        acc.x += vA.x * wA; acc.y += vA.y * wA; acc.z += vA.z * wA; acc.w += vA.w * wA;
        acc.x += vB.x * wB; acc.y += vB.y * wB; acc.z += vB.z * wB; acc.w += vB.w * wB;
    }
    if (j < s1) {
        int s = src[j];
        float w = dis[s];
        float4 v = ((const float4*)hw)[s * 32 + lane];
        acc.x += v.x * w; acc.y += v.y * w; acc.z += v.z * w; acc.w += v.w * w;
    }
    float d  = dis[node];
    float d2 = d * d;
    float4 hv = ((const float4*)hw)[node * 32 + lane];
    float4 bv = ((const float4*)b)[lane];
    float4 o;
    o.x = acc.x * d + hv.x * d2 + bv.x;
    o.y = acc.y * d + hv.y * d2 + bv.y;
    o.z = acc.z * d + hv.z * d2 + bv.z;
    o.w = acc.w * d + hv.w * d2 + bv.w;
    if (residual) {
        float4 p = ((const float4*)hprev)[node * 32 + lane];
        o.x += p.x; o.y += p.y; o.z += p.z; o.w += p.w;
    }
    o.x = (o.x > 0.f) ? o.x : NEG * o.x;
    o.y = (o.y > 0.f) ? o.y : NEG * o.y;
    o.z = (o.z > 0.f) ? o.z : NEG * o.z;
    o.w = (o.w > 0.f) ? o.w : NEG * o.w;
    ((float4*)hout)[node * 32 + lane] = o;
}

// ---------------- layer-3 pull fused with logits head ----------------
__global__ void k_pull_logits(const int* __restrict__ rowptr, const int* __restrict__ src,
                              const float* __restrict__ dis, const float* __restrict__ hw,
                              const float* __restrict__ b, const float* __restrict__ hprev,
                              const float* __restrict__ lw, const float* __restrict__ lb,
                              float* __restrict__ out, int n) {
    int gid  = blockIdx.x * blockDim.x + threadIdx.x;
    int node = gid >> 5;
    int lane = gid & 31;
    if (node >= n) return;
    int s0 = rowptr[node];
    int s1 = rowptr[node + 1];
    float4 acc = make_float4(0.f, 0.f, 0.f, 0.f);
    int j = s0;
    for (; j + 1 < s1; j += 2) {
        int sA = src[j], sB = src[j + 1];
        float wA = dis[sA], wB = dis[sB];
        float4 vA = ((const float4*)hw)[sA * 32 + lane];
        float4 vB = ((const float4*)hw)[sB * 32 + lane];
        acc.x += vA.x * wA; acc.y += vA.y * wA; acc.z += vA.z * wA; acc.w += vA.w * wA;
        acc.x += vB.x * wB; acc.y += vB.y * wB; acc.z += vB.z * wB; acc.w += vB.w * wB;
    }
    if (j < s1) {
        int s = src[j];
        float w = dis[s];
        float4 v = ((const float4*)hw)[s * 32 + lane];
        acc.x += v.x * w; acc.y += v.y * w; acc.z += v.z * w; acc.w += v.w * w;
    }
    float d  = dis[node];
    float d2 = d * d;
    float4 hv = ((const float4*)hw)[node * 32 + lane];
    float4 bv = ((const float4*)b)[lane];
    float4 p  = ((const float4*)hprev)[node * 32 + lane];
    float4 o;
    o.x = acc.x * d + hv.x * d2 + bv.x + p.x;
    o.y = acc.y * d + hv.y * d2 + bv.y + p.y;
    o.z = acc.z * d + hv.z * d2 + bv.z + p.z;
    o.w = acc.w * d + hv.w * d2 + bv.w + p.w;
    o.x = (o.x > 0.f) ? o.x : NEG * o.x;
    o.y = (o.y > 0.f) ? o.y : NEG * o.y;
    o.z = (o.z > 0.f) ? o.z : NEG * o.z;
    o.w = (o.w > 0.f) ? o.w : NEG * o.w;
    float4 wv = ((const float4*)lw)[lane];
    float s = o.x * wv.x + o.y * wv.y + o.z * wv.z + o.w * wv.w;
#pragma unroll
    for (int off = 16; off > 0; off >>= 1) s += __shfl_down_sync(0xffffffffu, s, off);
    if (lane == 0) out[node] = s + lb[0];
}

extern "C" void kernel_launch(void* const* d_in, const int* in_sizes, int n_in,
                              void* d_out, int out_size) {
    const float* x   = (const float*)d_in[0];
    const int*   ei  = (const int*)d_in[1];
    const float* W1  = (const float*)d_in[2];
    const float* b1  = (const float*)d_in[3];
    const float* W2  = (const float*)d_in[4];
    const float* b2  = (const float*)d_in[5];
    const float* W3  = (const float*)d_in[6];
    const float* b3  = (const float*)d_in[7];
    const float* lw  = (const float*)d_in[8];
    const float* lb  = (const float*)d_in[9];
    float* out = (float*)d_out;

    const int ne = in_sizes[1] / 2;      // 600000
    const int n  = in_sizes[0] / DD;     // 50000
    const int* row = ei;
    const int* col = ei + ne;

    int *cnt, *cur, *rowptr, *src, *bsum;
    float *dis, *hw, *h;
    cudaGetSymbolAddress((void**)&cnt,    g_cnt);
    cudaGetSymbolAddress((void**)&cur,    g_cur);
    cudaGetSymbolAddress((void**)&rowptr, g_rowptr);
    cudaGetSymbolAddress((void**)&src,    g_src);
    cudaGetSymbolAddress((void**)&bsum,   g_bsum);
    cudaGetSymbolAddress((void**)&dis,    g_dis);
    cudaGetSymbolAddress((void**)&hw,     g_hw);
    cudaGetSymbolAddress((void**)&h,      g_h);

    static int smem_set = 0;
    (void)smem_set;
    cudaFuncSetAttribute(k_gemm, cudaFuncAttributeMaxDynamicSharedMemorySize,
                         SMEM_FLOATS * sizeof(float));

    const int T = 256;
    int nb        = (n + SCAN_B - 1) / SCAN_B;
    int gemm_grid = (n + 127) / 128;
    int pull_grid = (int)(((long long)n * 32 + T - 1) / T);
    size_t smem   = SMEM_FLOATS * sizeof(float);

    // ---- CSC build (once, reused by all 3 layers) ----
    k_init  <<<(n + T - 1) / T, T>>>(cnt, cur, n);
    k_count <<<(ne + T - 1) / T, T>>>(col, cnt, ne);
    k_scan1 <<<nb, SCAN_B>>>(cnt, rowptr, bsum, dis, n);
    k_scan2 <<<1, SCAN_B>>>(bsum, nb);
    k_scan3 <<<nb, SCAN_B>>>(rowptr, bsum, n, ne);
    k_bucket<<<(ne + T - 1) / T, T>>>(row, col, rowptr, cur, src, ne);

    // ---- layer 1 ----
    k_gemm<<<gemm_grid, T, smem>>>(x, W1, hw, n);
    k_pull<<<pull_grid, T>>>(rowptr, src, dis, hw, b1, nullptr, h, n, 0);

    // ---- layer 2 ----
    k_gemm<<<gemm_grid, T, smem>>>(h, W2, hw, n);
    k_pull<<<pull_grid, T>>>(rowptr, src, dis, hw, b2, h, h, n, 1);

    // ---- layer 3 (fused with logits head) ----
    k_gemm<<<gemm_grid, T, smem>>>(h, W3, hw, n);
    k_pull_logits<<<pull_grid, T>>>(rowptr, src, dis, hw, b3, h, lw, lb, out, n);
}